// round 1
// baseline (speedup 1.0000x reference)
#include <cuda_runtime.h>
#include <cuda_bf16.h>
#include <cstdint>

// Problem constants
#define S    2048
#define Dm   2048
#define FF   8192
#define NH   32
#define HD   64
#define L    4096   // 2*S

// ---------------- scratch (device globals; no allocations) ----------------
__device__ float g_xln [L * Dm];      // [mem_ln ; h_ln]
__device__ float g_q   [S * Dm];      // queries (h half only)
__device__ float g_k   [L * Dm];
__device__ float g_v   [L * Dm];
__device__ float g_attn[S * Dm];      // attention output pre-Wo
__device__ float g_h   [S * Dm];      // post-attn residual
__device__ float g_h2  [S * Dm];      // ln2 output
__device__ float g_gate[S * FF];
__device__ float g_up  [S * FF];

// ---------------- LayerNorm: one block per row, D=2048 ----------------
__global__ __launch_bounds__(256) void ln_kernel(
    const float* __restrict__ X, const float* __restrict__ w,
    const float* __restrict__ b, float* __restrict__ out)
{
    int row = blockIdx.x;
    int tid = threadIdx.x;
    const float* xr = X + (size_t)row * Dm;
    float4 a = ((const float4*)xr)[tid * 2];
    float4 c = ((const float4*)xr)[tid * 2 + 1];
    float s  = a.x + a.y + a.z + a.w + c.x + c.y + c.z + c.w;
    float ss = a.x*a.x + a.y*a.y + a.z*a.z + a.w*a.w
             + c.x*c.x + c.y*c.y + c.z*c.z + c.w*c.w;
#pragma unroll
    for (int o = 16; o; o >>= 1) {
        s  += __shfl_xor_sync(0xffffffffu, s,  o);
        ss += __shfl_xor_sync(0xffffffffu, ss, o);
    }
    __shared__ float bs[8], bss[8];
    if ((tid & 31) == 0) { bs[tid >> 5] = s; bss[tid >> 5] = ss; }
    __syncthreads();
    float ts = 0.f, tss = 0.f;
#pragma unroll
    for (int i = 0; i < 8; i++) { ts += bs[i]; tss += bss[i]; }
    float mean = ts * (1.f / Dm);
    float var  = tss * (1.f / Dm) - mean * mean;
    float inv  = rsqrtf(var + 1e-5f);

    int d = tid * 8;
    float4 w0 = ((const float4*)w)[tid*2],   w1 = ((const float4*)w)[tid*2+1];
    float4 b0 = ((const float4*)b)[tid*2],   b1 = ((const float4*)b)[tid*2+1];
    float4 o0, o1;
    o0.x = (a.x-mean)*inv*w0.x + b0.x;  o0.y = (a.y-mean)*inv*w0.y + b0.y;
    o0.z = (a.z-mean)*inv*w0.z + b0.z;  o0.w = (a.w-mean)*inv*w0.w + b0.w;
    o1.x = (c.x-mean)*inv*w1.x + b1.x;  o1.y = (c.y-mean)*inv*w1.y + b1.y;
    o1.z = (c.z-mean)*inv*w1.z + b1.z;  o1.w = (c.w-mean)*inv*w1.w + b1.w;
    float* orow = out + (size_t)row * Dm + d;
    ((float4*)orow)[0] = o0;
    ((float4*)orow)[1] = o1;
}

// ---------------- SGEMM: C[M,N] = A[M,K] @ B[N,K]^T (+ Res) ----------------
// 128x128 tile, K-step 8, 256 threads, 8x8 per-thread microtile.
__global__ __launch_bounds__(256) void sgemm_nt(
    const float* __restrict__ A, const float* __restrict__ B,
    const float* __restrict__ Res, float* __restrict__ C,
    int M, int N, int K)
{
    __shared__ float As[8][128];
    __shared__ float Bs[8][128];
    int tid = threadIdx.x;
    int bm = blockIdx.y * 128;
    int bn = blockIdx.x * 128;
    int tm = (tid >> 4) << 3;
    int tn = (tid & 15) << 3;
    int lr = tid >> 1;
    int lc = (tid & 1) << 2;
    const float* Aptr = A + (size_t)(bm + lr) * K + lc;
    const float* Bptr = B + (size_t)(bn + lr) * K + lc;

    float acc[8][8];
#pragma unroll
    for (int i = 0; i < 8; i++)
#pragma unroll
        for (int j = 0; j < 8; j++) acc[i][j] = 0.f;

    for (int k0 = 0; k0 < K; k0 += 8) {
        float4 a4 = *(const float4*)(Aptr + k0);
        float4 b4 = *(const float4*)(Bptr + k0);
        __syncthreads();
        As[lc+0][lr] = a4.x; As[lc+1][lr] = a4.y;
        As[lc+2][lr] = a4.z; As[lc+3][lr] = a4.w;
        Bs[lc+0][lr] = b4.x; Bs[lc+1][lr] = b4.y;
        Bs[lc+2][lr] = b4.z; Bs[lc+3][lr] = b4.w;
        __syncthreads();
#pragma unroll
        for (int kk = 0; kk < 8; kk++) {
            float af[8], bf[8];
            *(float4*)(af)     = *(const float4*)&As[kk][tm];
            *(float4*)(af + 4) = *(const float4*)&As[kk][tm + 4];
            *(float4*)(bf)     = *(const float4*)&Bs[kk][tn];
            *(float4*)(bf + 4) = *(const float4*)&Bs[kk][tn + 4];
#pragma unroll
            for (int i = 0; i < 8; i++)
#pragma unroll
                for (int j = 0; j < 8; j++)
                    acc[i][j] += af[i] * bf[j];
        }
    }

#pragma unroll
    for (int i = 0; i < 8; i++) {
        size_t off = (size_t)(bm + tm + i) * N + bn + tn;
        float4 r0 = make_float4(acc[i][0], acc[i][1], acc[i][2], acc[i][3]);
        float4 r1 = make_float4(acc[i][4], acc[i][5], acc[i][6], acc[i][7]);
        if (Res) {
            float4 e0 = *(const float4*)(Res + off);
            float4 e1 = *(const float4*)(Res + off + 4);
            r0.x += e0.x; r0.y += e0.y; r0.z += e0.z; r0.w += e0.w;
            r1.x += e1.x; r1.y += e1.y; r1.z += e1.z; r1.w += e1.w;
        }
        *(float4*)(C + off)     = r0;
        *(float4*)(C + off + 4) = r1;
    }
}

// ---------------- partial RoPE on first 16 dims of each head ----------------
__global__ __launch_bounds__(256) void rope_kernel(float* __restrict__ X, int rows)
{
    int row = blockIdx.x;           // one block per row (256 = 32 heads * 8 pairs)
    if (row >= rows) return;
    int r = threadIdx.x;
    int h = r >> 3, d = r & 7;
    int pos = row & (S - 1);        // concat halves share positions
    float invf = __powf(10000.f, -(float)d * 0.125f);
    float ang  = (float)pos * invf;
    float sn, cs;
    sincosf(ang, &sn, &cs);
    float* p = X + (size_t)row * Dm + h * HD;
    float x1 = p[d], x2 = p[d + 8];
    p[d]     = x1 * cs - x2 * sn;
    p[d + 8] = x2 * cs + x1 * sn;
}

// ---------------- sparse attention ----------------
// Query i attends to memory keys j < i  (K/V rows 0..S-1) plus the self token
// (K/V row S+i). Flash-style online softmax: 64 queries/block, 32 keys/iter.
#define AM 64
#define AN 32
__global__ __launch_bounds__(256) void attn_kernel(
    const float* __restrict__ Q, const float* __restrict__ K,
    const float* __restrict__ V, float* __restrict__ O)
{
    __shared__ float qs[AM][65];
    __shared__ float ks[AN][65];
    __shared__ float vs[AN][65];
    __shared__ float ps[AM][33];
    __shared__ float red[AM][8];

    int qb = blockIdx.x;
    int h  = blockIdx.y;
    int tid = threadIdx.x;
    int m  = tid >> 2;          // query row in tile (0..63)
    int q4 = tid & 3;           // quarter: 8 score cols, 16 out dims
    int i  = qb * AM + m;       // global query index

    // load Q tile (each thread: its row's 16 dims)
    {
        const float* qrow = Q + (size_t)i * Dm + h * HD + q4 * 16;
#pragma unroll
        for (int t = 0; t < 4; t++) {
            float4 v4 = *(const float4*)(qrow + t * 4);
            qs[m][q4*16 + t*4 + 0] = v4.x;
            qs[m][q4*16 + t*4 + 1] = v4.y;
            qs[m][q4*16 + t*4 + 2] = v4.z;
            qs[m][q4*16 + t*4 + 3] = v4.w;
        }
    }

    float mi = -1e30f, li = 0.f;
    float acc[16];
#pragma unroll
    for (int t = 0; t < 16; t++) acc[t] = 0.f;

    int kbmax = 2 * qb + 1;     // cover memory keys 0 .. qb*64+63
    for (int kb = 0; kb <= kbmax; kb++) {
        __syncthreads();
        {   // load K/V tile: 32 rows x 64 dims
            int lr = tid >> 3;
            int lcc = (tid & 7) * 8;
            const float* kp = K + (size_t)(kb * AN + lr) * Dm + h * HD + lcc;
            const float* vp = V + (size_t)(kb * AN + lr) * Dm + h * HD + lcc;
            float4 a = *(const float4*)kp, b = *(const float4*)(kp + 4);
            ks[lr][lcc+0]=a.x; ks[lr][lcc+1]=a.y; ks[lr][lcc+2]=a.z; ks[lr][lcc+3]=a.w;
            ks[lr][lcc+4]=b.x; ks[lr][lcc+5]=b.y; ks[lr][lcc+6]=b.z; ks[lr][lcc+7]=b.w;
            float4 c = *(const float4*)vp, d = *(const float4*)(vp + 4);
            vs[lr][lcc+0]=c.x; vs[lr][lcc+1]=c.y; vs[lr][lcc+2]=c.z; vs[lr][lcc+3]=c.w;
            vs[lr][lcc+4]=d.x; vs[lr][lcc+5]=d.y; vs[lr][lcc+6]=d.z; vs[lr][lcc+7]=d.w;
        }
        __syncthreads();

        // scores for keys [kb*32 + q4*8 .. +7]
        float sc[8];
#pragma unroll
        for (int n = 0; n < 8; n++) sc[n] = 0.f;
#pragma unroll
        for (int d = 0; d < HD; d++) {
            float qd = qs[m][d];
#pragma unroll
            for (int n = 0; n < 8; n++)
                sc[n] += qd * ks[q4*8 + n][d];
        }
        float lmax = -1e30f;
#pragma unroll
        for (int n = 0; n < 8; n++) {
            int j = kb * AN + q4 * 8 + n;
            float sv = sc[n] * 0.125f;
            if (j >= i) sv = -1e30f;     // strict j < i
            sc[n] = sv;
            lmax = fmaxf(lmax, sv);
        }
        red[m][q4] = lmax;
        __syncthreads();
        float rmax = fmaxf(fmaxf(red[m][0], red[m][1]), fmaxf(red[m][2], red[m][3]));
        float newm = fmaxf(mi, rmax);
        float scale = __expf(mi - newm);
        float lsum = 0.f;
#pragma unroll
        for (int n = 0; n < 8; n++) {
            float p = (sc[n] <= -1e29f) ? 0.f : __expf(sc[n] - newm);
            ps[m][q4*8 + n] = p;
            lsum += p;
        }
        red[m][4 + q4] = lsum;
        __syncthreads();
        float rsum = red[m][4] + red[m][5] + red[m][6] + red[m][7];
        mi = newm;
        li = li * scale + rsum;
#pragma unroll
        for (int t = 0; t < 16; t++) acc[t] *= scale;
        for (int n = 0; n < AN; n++) {
            float p = ps[m][n];
#pragma unroll
            for (int t = 0; t < 16; t++)
                acc[t] += p * vs[n][q4*16 + t];
        }
    }

    // self token: K/V row S + i
    {
        const float* krow = K + (size_t)(S + i) * Dm + h * HD + q4 * 16;
        float part = 0.f;
#pragma unroll
        for (int t = 0; t < 16; t++) part += qs[m][q4*16 + t] * krow[t];
        __syncthreads();
        red[m][q4] = part;
        __syncthreads();
        float sself = 0.125f * (red[m][0] + red[m][1] + red[m][2] + red[m][3]);
        float newm = fmaxf(mi, sself);
        float scale = __expf(mi - newm);
        float p = __expf(sself - newm);
        li = li * scale + p;
        float inv = 1.f / li;
        const float* vrow = V + (size_t)(S + i) * Dm + h * HD + q4 * 16;
        float* orow = O + (size_t)i * Dm + h * HD + q4 * 16;
#pragma unroll
        for (int t = 0; t < 16; t++)
            orow[t] = (acc[t] * scale + p * vrow[t]) * inv;
    }
}

// ---------------- SiLU(gate) * up, in place into gate ----------------
__global__ __launch_bounds__(256) void silu_mul_kernel(
    float* __restrict__ G, const float* __restrict__ U, int n4)
{
    int idx = blockIdx.x * blockDim.x + threadIdx.x;
    if (idx >= n4) return;
    float4 g = ((float4*)G)[idx];
    float4 u = ((const float4*)U)[idx];
    g.x = g.x / (1.f + __expf(-g.x)) * u.x;
    g.y = g.y / (1.f + __expf(-g.y)) * u.y;
    g.z = g.z / (1.f + __expf(-g.z)) * u.z;
    g.w = g.w / (1.f + __expf(-g.w)) * u.w;
    ((float4*)G)[idx] = g;
}

// ---------------- launch ----------------
extern "C" void kernel_launch(void* const* d_in, const int* in_sizes, int n_in,
                              void* d_out, int out_size)
{
    const float* hidden = (const float*)d_in[0];
    const float* memory = (const float*)d_in[1];
    // d_in[2] attention_mask (structural — unused), d_in[3] position_ids (arange — unused)
    const float* ln1w = (const float*)d_in[4];
    const float* ln1b = (const float*)d_in[5];
    const float* ln2w = (const float*)d_in[6];
    const float* ln2b = (const float*)d_in[7];
    const float* Wq = (const float*)d_in[8];
    const float* Wk = (const float*)d_in[9];
    const float* Wv = (const float*)d_in[10];
    const float* Wo = (const float*)d_in[11];
    const float* Wg = (const float*)d_in[12];
    const float* Wu = (const float*)d_in[13];
    const float* Wd = (const float*)d_in[14];
    float* out = (float*)d_out;

    void* p;
    cudaGetSymbolAddress(&p, g_xln);  float* xln  = (float*)p;
    cudaGetSymbolAddress(&p, g_q);    float* q    = (float*)p;
    cudaGetSymbolAddress(&p, g_k);    float* k    = (float*)p;
    cudaGetSymbolAddress(&p, g_v);    float* v    = (float*)p;
    cudaGetSymbolAddress(&p, g_attn); float* attn = (float*)p;
    cudaGetSymbolAddress(&p, g_h);    float* hbuf = (float*)p;
    cudaGetSymbolAddress(&p, g_h2);   float* h2   = (float*)p;
    cudaGetSymbolAddress(&p, g_gate); float* gate = (float*)p;
    cudaGetSymbolAddress(&p, g_up);   float* up   = (float*)p;

    // 1. LN of memory -> xln[0:S], LN of hidden -> xln[S:2S]
    ln_kernel<<<S, 256>>>(memory, ln1w, ln1b, xln);
    ln_kernel<<<S, 256>>>(hidden, ln1w, ln1b, xln + (size_t)S * Dm);

    // 2. K, V over all L rows; Q over h half only
    {
        dim3 gKV(Dm / 128, L / 128);
        sgemm_nt<<<gKV, 256>>>(xln, Wk, nullptr, k, L, Dm, Dm);
        sgemm_nt<<<gKV, 256>>>(xln, Wv, nullptr, v, L, Dm, Dm);
        dim3 gQ(Dm / 128, S / 128);
        sgemm_nt<<<gQ, 256>>>(xln + (size_t)S * Dm, Wq, nullptr, q, S, Dm, Dm);
    }

    // 3. RoPE (first 16 dims of each head)
    rope_kernel<<<S, 256>>>(q, S);
    rope_kernel<<<L, 256>>>(k, L);

    // 4. sparse attention
    {
        dim3 g(S / AM, NH);
        attn_kernel<<<g, 256>>>(q, k, v, attn);
    }

    // 5. output projection + residual
    {
        dim3 g(Dm / 128, S / 128);
        sgemm_nt<<<g, 256>>>(attn, Wo, hidden, hbuf, S, Dm, Dm);
    }

    // 6. LN2
    ln_kernel<<<S, 256>>>(hbuf, ln2w, ln2b, h2);

    // 7. gate/up projections
    {
        dim3 g(FF / 128, S / 128);
        sgemm_nt<<<g, 256>>>(h2, Wg, nullptr, gate, S, FF, Dm);
        sgemm_nt<<<g, 256>>>(h2, Wu, nullptr, up, S, FF, Dm);
    }

    // 8. silu(gate) * up (in place)
    {
        int n4 = S * FF / 4;
        silu_mul_kernel<<<(n4 + 255) / 256, 256>>>(gate, up, n4);
    }

    // 9. down projection + residual -> output
    {
        dim3 g(Dm / 128, S / 128);
        sgemm_nt<<<g, 256>>>(gate, Wd, hbuf, out, S, Dm, FF);
    }
}

// round 3
// speedup vs baseline: 1.8794x; 1.8794x over previous
#include <cuda_runtime.h>
#include <cuda_bf16.h>
#include <cstdint>

// Problem constants
#define S    2048
#define Dm   2048
#define FF   8192
#define NH   32
#define HD   64
#define L    4096   // 2*S

typedef __nv_bfloat16 bf16;

// ===================== helpers =====================
__device__ __forceinline__ uint32_t smem_u32(const void* p) {
    uint32_t a;
    asm("{ .reg .u64 t; cvta.to.shared.u64 t, %1; cvt.u32.u64 %0, t; }" : "=r"(a) : "l"(p));
    return a;
}
__device__ __forceinline__ void ldm_x4(uint32_t* r, uint32_t a) {
    asm volatile("ldmatrix.sync.aligned.m8n8.x4.shared.b16 {%0,%1,%2,%3}, [%4];"
        : "=r"(r[0]), "=r"(r[1]), "=r"(r[2]), "=r"(r[3]) : "r"(a));
}
__device__ __forceinline__ void mma_bf16(float* c, const uint32_t* a, uint32_t b0, uint32_t b1) {
    asm volatile("mma.sync.aligned.m16n8k16.row.col.f32.bf16.bf16.f32 "
        "{%0,%1,%2,%3}, {%4,%5,%6,%7}, {%8,%9}, {%0,%1,%2,%3};"
        : "+f"(c[0]), "+f"(c[1]), "+f"(c[2]), "+f"(c[3])
        : "r"(a[0]), "r"(a[1]), "r"(a[2]), "r"(a[3]), "r"(b0), "r"(b1));
}
#define CP_ASYNC16(dst, src) \
    asm volatile("cp.async.cg.shared.global [%0], [%1], 16;" :: "r"(dst), "l"(src))
#define CP_COMMIT() asm volatile("cp.async.commit_group;" ::: "memory")
#define CP_WAIT2()  asm volatile("cp.async.wait_group 2;" ::: "memory")

// ===================== scratch (device globals) =====================
__device__ bf16  g_xh [L * Dm];       // ln1 output hi
__device__ bf16  g_xl [L * Dm];       // ln1 output lo
__device__ float g_q  [S * Dm];
__device__ float g_k  [L * Dm];
__device__ float g_v  [L * Dm];
__device__ bf16  g_ah [S * Dm];       // attn out hi
__device__ bf16  g_al [S * Dm];
__device__ float g_h  [S * Dm];       // post-attn residual
__device__ bf16  g_h2h[S * Dm];
__device__ bf16  g_h2l[S * Dm];
__device__ float g_gr [S * FF];       // gate raw
__device__ float g_ur [S * FF];       // up raw
__device__ bf16  g_gh [S * FF];       // silu(gate)*up hi
__device__ bf16  g_gl [S * FF];
__device__ bf16  g_wqh[Dm * Dm]; __device__ bf16 g_wql[Dm * Dm];
__device__ bf16  g_wkh[Dm * Dm]; __device__ bf16 g_wkl[Dm * Dm];
__device__ bf16  g_wvh[Dm * Dm]; __device__ bf16 g_wvl[Dm * Dm];
__device__ bf16  g_woh[Dm * Dm]; __device__ bf16 g_wol[Dm * Dm];
__device__ bf16  g_wgh[FF * Dm]; __device__ bf16 g_wgl[FF * Dm];
__device__ bf16  g_wuh[FF * Dm]; __device__ bf16 g_wul[FF * Dm];
__device__ bf16  g_wdh[Dm * FF]; __device__ bf16 g_wdl[Dm * FF];

// ===================== bf16 hi/lo split of a tensor =====================
__global__ __launch_bounds__(256) void split_kernel(
    const float* __restrict__ X, bf16* __restrict__ H, bf16* __restrict__ Lo, int n4)
{
    int i = blockIdx.x * blockDim.x + threadIdx.x;
    if (i >= n4) return;
    float4 x = ((const float4*)X)[i];
    bf16 h0 = __float2bfloat16_rn(x.x), h1 = __float2bfloat16_rn(x.y);
    bf16 h2 = __float2bfloat16_rn(x.z), h3 = __float2bfloat16_rn(x.w);
    bf16 l0 = __float2bfloat16_rn(x.x - __bfloat162float(h0));
    bf16 l1 = __float2bfloat16_rn(x.y - __bfloat162float(h1));
    bf16 l2 = __float2bfloat16_rn(x.z - __bfloat162float(h2));
    bf16 l3 = __float2bfloat16_rn(x.w - __bfloat162float(h3));
    __nv_bfloat162 hv0 = {h0, h1}, hv1 = {h2, h3};
    __nv_bfloat162 lv0 = {l0, l1}, lv1 = {l2, l3};
    uint2 hu, lu;
    hu.x = *(uint32_t*)&hv0; hu.y = *(uint32_t*)&hv1;
    lu.x = *(uint32_t*)&lv0; lu.y = *(uint32_t*)&lv1;
    ((uint2*)H)[i]  = hu;
    ((uint2*)Lo)[i] = lu;
}

// ===================== LayerNorm with fused bf16 split =====================
__global__ __launch_bounds__(256) void ln_split_kernel(
    const float* __restrict__ X, const float* __restrict__ w,
    const float* __restrict__ b, bf16* __restrict__ OH, bf16* __restrict__ OL)
{
    int row = blockIdx.x;
    int tid = threadIdx.x;
    const float* xr = X + (size_t)row * Dm;
    float4 a = ((const float4*)xr)[tid * 2];
    float4 c = ((const float4*)xr)[tid * 2 + 1];
    float s  = a.x + a.y + a.z + a.w + c.x + c.y + c.z + c.w;
    float ss = a.x*a.x + a.y*a.y + a.z*a.z + a.w*a.w
             + c.x*c.x + c.y*c.y + c.z*c.z + c.w*c.w;
#pragma unroll
    for (int o = 16; o; o >>= 1) {
        s  += __shfl_xor_sync(0xffffffffu, s,  o);
        ss += __shfl_xor_sync(0xffffffffu, ss, o);
    }
    __shared__ float bs[8], bss[8];
    if ((tid & 31) == 0) { bs[tid >> 5] = s; bss[tid >> 5] = ss; }
    __syncthreads();
    float ts = 0.f, tss = 0.f;
#pragma unroll
    for (int i = 0; i < 8; i++) { ts += bs[i]; tss += bss[i]; }
    float mean = ts * (1.f / Dm);
    float var  = tss * (1.f / Dm) - mean * mean;
    float inv  = rsqrtf(var + 1e-5f);

    int d = tid * 8;
    float4 w0 = ((const float4*)w)[tid*2], w1 = ((const float4*)w)[tid*2+1];
    float4 b0 = ((const float4*)b)[tid*2], b1 = ((const float4*)b)[tid*2+1];
    float v8[8];
    v8[0]=(a.x-mean)*inv*w0.x+b0.x; v8[1]=(a.y-mean)*inv*w0.y+b0.y;
    v8[2]=(a.z-mean)*inv*w0.z+b0.z; v8[3]=(a.w-mean)*inv*w0.w+b0.w;
    v8[4]=(c.x-mean)*inv*w1.x+b1.x; v8[5]=(c.y-mean)*inv*w1.y+b1.y;
    v8[6]=(c.z-mean)*inv*w1.z+b1.z; v8[7]=(c.w-mean)*inv*w1.w+b1.w;
    uint16_t h8[8], l8[8];
#pragma unroll
    for (int i = 0; i < 8; i++) {
        bf16 hv = __float2bfloat16_rn(v8[i]);
        bf16 lv = __float2bfloat16_rn(v8[i] - __bfloat162float(hv));
        h8[i] = *(uint16_t*)&hv;
        l8[i] = *(uint16_t*)&lv;
    }
    *(uint4*)(OH + (size_t)row * Dm + d) = *(uint4*)h8;
    *(uint4*)(OL + (size_t)row * Dm + d) = *(uint4*)l8;
}

// ===================== bf16 mma.sync GEMM, 3-term compensated =====================
// C[M,N] = (Ahi+Alo)[M,K] @ (Bhi+Blo)[N,K]^T (+Res)
// 128x128 tile, BK=32, 3 cp.async stages, 8 warps = 4(M) x 2(N), warp tile 32x64.
#define GBK 32
#define G_ROWB 80                         // 32 bf16 (64B) + 16B pad
#define G_TILEB (128 * G_ROWB)            // 10240
#define G_STAGEB (4 * G_TILEB)            // 40960 (Ah, Al, Bh, Bl)
#define G_DSMEM (3 * G_STAGEB)            // 122880

__global__ __launch_bounds__(256, 1)
void gemm3_bf16(const bf16* __restrict__ Ahi, const bf16* __restrict__ Alo,
                const bf16* __restrict__ Bhi, const bf16* __restrict__ Blo,
                const float* __restrict__ Res, float* __restrict__ C,
                int M, int N, int K)
{
    extern __shared__ char smem[];
    uint32_t sb = smem_u32(smem);
    int tid  = threadIdx.x;
    int wid  = tid >> 5;
    int lane = tid & 31;
    int wm = wid & 3;          // 4 warps over M (32 rows each)
    int wn = wid >> 2;         // 2 warps over N (64 cols each)
    int bm = blockIdx.y * 128;
    int bn = blockIdx.x * 128;

    // cp.async load of one 32-k chunk: 4 tiles of 128 rows x 32 bf16
    auto loadChunk = [&](int stg, int k0) {
        uint32_t base = sb + stg * G_STAGEB;
#pragma unroll
        for (int h = 0; h < 2; h++) {
            int cid = tid * 2 + h;          // 0..511
            int r = cid >> 2;
            int c = cid & 3;
            uint32_t doff = r * G_ROWB + c * 16;
            size_t soff = (size_t)r * K + k0 + c * 8;
            CP_ASYNC16(base + doff,             Ahi + (size_t)bm * K + soff);
            CP_ASYNC16(base + G_TILEB + doff,   Alo + (size_t)bm * K + soff);
            CP_ASYNC16(base + 2*G_TILEB + doff, Bhi + (size_t)bn * K + soff);
            CP_ASYNC16(base + 3*G_TILEB + doff, Blo + (size_t)bn * K + soff);
        }
    };

    float acc[2][8][4];
#pragma unroll
    for (int i = 0; i < 2; i++)
#pragma unroll
        for (int j = 0; j < 8; j++)
#pragma unroll
            for (int t = 0; t < 4; t++) acc[i][j][t] = 0.f;

    // ldmatrix lane-address components
    int a_row = ((lane >> 3) & 1) * 8 + (lane & 7);   // + kbyte (lane>>4)*16
    int b_row = (lane & 7);                            // + nfrag sel ((lane>>4)&1)
    int b_kb  = ((lane >> 3) & 1) * 16;

    int NKC = K / GBK;
    loadChunk(0, 0);        CP_COMMIT();
    loadChunk(1, GBK);      CP_COMMIT();
    loadChunk(2, 2 * GBK);  CP_COMMIT();

    for (int k = 0; k < NKC; k++) {
        int stg = k % 3;
        CP_WAIT2();
        __syncthreads();
        uint32_t base = sb + stg * G_STAGEB;
#pragma unroll
        for (int kk = 0; kk < 2; kk++) {
            uint32_t Ah[2][4], Al[2][4];
#pragma unroll
            for (int mf = 0; mf < 2; mf++) {
                uint32_t addr = base + (uint32_t)((wm*32 + mf*16 + a_row) * G_ROWB)
                              + kk*32 + (lane >> 4) * 16;
                ldm_x4(Ah[mf], addr);
                ldm_x4(Al[mf], addr + G_TILEB);
            }
#pragma unroll
            for (int g = 0; g < 2; g++) {
                uint32_t Bh[4][2], Bl[4][2];
#pragma unroll
                for (int p = 0; p < 2; p++) {
                    uint32_t addr = base + 2*G_TILEB
                        + (uint32_t)((wn*64 + (g*4 + p*2 + ((lane>>4)&1))*8 + b_row) * G_ROWB)
                        + kk*32 + b_kb;
                    uint32_t r4[4];
                    ldm_x4(r4, addr);
                    Bh[p*2][0] = r4[0]; Bh[p*2][1] = r4[1];
                    Bh[p*2+1][0] = r4[2]; Bh[p*2+1][1] = r4[3];
                    ldm_x4(r4, addr + G_TILEB);
                    Bl[p*2][0] = r4[0]; Bl[p*2][1] = r4[1];
                    Bl[p*2+1][0] = r4[2]; Bl[p*2+1][1] = r4[3];
                }
#pragma unroll
                for (int mf = 0; mf < 2; mf++)
#pragma unroll
                    for (int nf = 0; nf < 4; nf++) {
                        float* c = acc[mf][g*4 + nf];
                        mma_bf16(c, Ah[mf], Bh[nf][0], Bh[nf][1]);
                        mma_bf16(c, Al[mf], Bh[nf][0], Bh[nf][1]);
                        mma_bf16(c, Ah[mf], Bl[nf][0], Bl[nf][1]);
                    }
            }
        }
        __syncthreads();
        if (k + 3 < NKC) loadChunk(stg, (k + 3) * GBK);
        CP_COMMIT();
    }

    // Epilogue: direct float2 stores (+optional residual)
    int rr = lane >> 2;
    int cp = lane & 3;
#pragma unroll
    for (int mf = 0; mf < 2; mf++) {
        int row0 = bm + wm*32 + mf*16 + rr;
#pragma unroll
        for (int nf = 0; nf < 8; nf++) {
            int col = bn + wn*64 + nf*8 + cp*2;
            float* c = acc[mf][nf];
            size_t o0 = (size_t)row0 * N + col;
            size_t o1 = (size_t)(row0 + 8) * N + col;
            float2 v0 = make_float2(c[0], c[1]);
            float2 v1 = make_float2(c[2], c[3]);
            if (Res) {
                float2 e0 = *(const float2*)(Res + o0);
                float2 e1 = *(const float2*)(Res + o1);
                v0.x += e0.x; v0.y += e0.y;
                v1.x += e1.x; v1.y += e1.y;
            }
            *(float2*)(C + o0) = v0;
            *(float2*)(C + o1) = v1;
        }
    }
}

// ---------------- partial RoPE on first 16 dims of each head ----------------
__global__ __launch_bounds__(256) void rope_kernel(float* __restrict__ X, int rows)
{
    int row = blockIdx.x;
    if (row >= rows) return;
    int r = threadIdx.x;
    int h = r >> 3, d = r & 7;
    int pos = row & (S - 1);
    float invf = __powf(10000.f, -(float)d * 0.125f);
    float ang  = (float)pos * invf;
    float sn, cs;
    sincosf(ang, &sn, &cs);
    float* p = X + (size_t)row * Dm + h * HD;
    float x1 = p[d], x2 = p[d + 8];
    p[d]     = x1 * cs - x2 * sn;
    p[d + 8] = x2 * cs + x1 * sn;
}

// ---------------- sparse attention (fp32), epilogue writes bf16 hi/lo -------
#define AM 64
#define AN 32
__global__ __launch_bounds__(256) void attn_kernel(
    const float* __restrict__ Q, const float* __restrict__ K,
    const float* __restrict__ V, bf16* __restrict__ OH, bf16* __restrict__ OL)
{
    __shared__ float qs[AM][65];
    __shared__ float ks[AN][65];
    __shared__ float vs[AN][65];
    __shared__ float ps[AM][33];
    __shared__ float red[AM][8];

    int qb = blockIdx.x;
    int h  = blockIdx.y;
    int tid = threadIdx.x;
    int m  = tid >> 2;
    int q4 = tid & 3;
    int i  = qb * AM + m;

    {
        const float* qrow = Q + (size_t)i * Dm + h * HD + q4 * 16;
#pragma unroll
        for (int t = 0; t < 4; t++) {
            float4 v4 = *(const float4*)(qrow + t * 4);
            qs[m][q4*16 + t*4 + 0] = v4.x;
            qs[m][q4*16 + t*4 + 1] = v4.y;
            qs[m][q4*16 + t*4 + 2] = v4.z;
            qs[m][q4*16 + t*4 + 3] = v4.w;
        }
    }

    float mi = -1e30f, li = 0.f;
    float acc[16];
#pragma unroll
    for (int t = 0; t < 16; t++) acc[t] = 0.f;

    int kbmax = 2 * qb + 1;
    for (int kb = 0; kb <= kbmax; kb++) {
        __syncthreads();
        {
            int lr = tid >> 3;
            int lcc = (tid & 7) * 8;
            const float* kp = K + (size_t)(kb * AN + lr) * Dm + h * HD + lcc;
            const float* vp = V + (size_t)(kb * AN + lr) * Dm + h * HD + lcc;
            float4 a = *(const float4*)kp, b = *(const float4*)(kp + 4);
            ks[lr][lcc+0]=a.x; ks[lr][lcc+1]=a.y; ks[lr][lcc+2]=a.z; ks[lr][lcc+3]=a.w;
            ks[lr][lcc+4]=b.x; ks[lr][lcc+5]=b.y; ks[lr][lcc+6]=b.z; ks[lr][lcc+7]=b.w;
            float4 c = *(const float4*)vp, d = *(const float4*)(vp + 4);
            vs[lr][lcc+0]=c.x; vs[lr][lcc+1]=c.y; vs[lr][lcc+2]=c.z; vs[lr][lcc+3]=c.w;
            vs[lr][lcc+4]=d.x; vs[lr][lcc+5]=d.y; vs[lr][lcc+6]=d.z; vs[lr][lcc+7]=d.w;
        }
        __syncthreads();

        float sc[8];
#pragma unroll
        for (int n = 0; n < 8; n++) sc[n] = 0.f;
#pragma unroll
        for (int d = 0; d < HD; d++) {
            float qd = qs[m][d];
#pragma unroll
            for (int n = 0; n < 8; n++)
                sc[n] += qd * ks[q4*8 + n][d];
        }
        float lmax = -1e30f;
#pragma unroll
        for (int n = 0; n < 8; n++) {
            int j = kb * AN + q4 * 8 + n;
            float sv = sc[n] * 0.125f;
            if (j >= i) sv = -1e30f;
            sc[n] = sv;
            lmax = fmaxf(lmax, sv);
        }
        red[m][q4] = lmax;
        __syncthreads();
        float rmax = fmaxf(fmaxf(red[m][0], red[m][1]), fmaxf(red[m][2], red[m][3]));
        float newm = fmaxf(mi, rmax);
        float scale = __expf(mi - newm);
        float lsum = 0.f;
#pragma unroll
        for (int n = 0; n < 8; n++) {
            float p = (sc[n] <= -1e29f) ? 0.f : __expf(sc[n] - newm);
            ps[m][q4*8 + n] = p;
            lsum += p;
        }
        red[m][4 + q4] = lsum;
        __syncthreads();
        float rsum = red[m][4] + red[m][5] + red[m][6] + red[m][7];
        mi = newm;
        li = li * scale + rsum;
#pragma unroll
        for (int t = 0; t < 16; t++) acc[t] *= scale;
        for (int n = 0; n < AN; n++) {
            float p = ps[m][n];
#pragma unroll
            for (int t = 0; t < 16; t++)
                acc[t] += p * vs[n][q4*16 + t];
        }
    }

    {
        const float* krow = K + (size_t)(S + i) * Dm + h * HD + q4 * 16;
        float part = 0.f;
#pragma unroll
        for (int t = 0; t < 16; t++) part += qs[m][q4*16 + t] * krow[t];
        __syncthreads();
        red[m][q4] = part;
        __syncthreads();
        float sself = 0.125f * (red[m][0] + red[m][1] + red[m][2] + red[m][3]);
        float newm = fmaxf(mi, sself);
        float scale = __expf(mi - newm);
        float p = __expf(sself - newm);
        li = li * scale + p;
        float inv = 1.f / li;
        const float* vrow = V + (size_t)(S + i) * Dm + h * HD + q4 * 16;
        uint16_t h16[16], l16[16];
#pragma unroll
        for (int t = 0; t < 16; t++) {
            float val = (acc[t] * scale + p * vrow[t]) * inv;
            bf16 hv = __float2bfloat16_rn(val);
            bf16 lv = __float2bfloat16_rn(val - __bfloat162float(hv));
            h16[t] = *(uint16_t*)&hv;
            l16[t] = *(uint16_t*)&lv;
        }
        bf16* orh = OH + (size_t)i * Dm + h * HD + q4 * 16;
        bf16* orl = OL + (size_t)i * Dm + h * HD + q4 * 16;
        *(uint4*)(orh)     = *(uint4*)(h16);
        *(uint4*)(orh + 8) = *(uint4*)(h16 + 8);
        *(uint4*)(orl)     = *(uint4*)(l16);
        *(uint4*)(orl + 8) = *(uint4*)(l16 + 8);
    }
}

// ---------------- SiLU(gate) * up with fused bf16 split ----------------
__global__ __launch_bounds__(256) void silu_split_kernel(
    const float* __restrict__ G, const float* __restrict__ U,
    bf16* __restrict__ OH, bf16* __restrict__ OL, int n4)
{
    int idx = blockIdx.x * blockDim.x + threadIdx.x;
    if (idx >= n4) return;
    float4 g = ((const float4*)G)[idx];
    float4 u = ((const float4*)U)[idx];
    float v[4];
    v[0] = g.x / (1.f + __expf(-g.x)) * u.x;
    v[1] = g.y / (1.f + __expf(-g.y)) * u.y;
    v[2] = g.z / (1.f + __expf(-g.z)) * u.z;
    v[3] = g.w / (1.f + __expf(-g.w)) * u.w;
    uint16_t h4[4], l4[4];
#pragma unroll
    for (int i = 0; i < 4; i++) {
        bf16 hv = __float2bfloat16_rn(v[i]);
        bf16 lv = __float2bfloat16_rn(v[i] - __bfloat162float(hv));
        h4[i] = *(uint16_t*)&hv;
        l4[i] = *(uint16_t*)&lv;
    }
    ((uint2*)OH)[idx] = *(uint2*)h4;
    ((uint2*)OL)[idx] = *(uint2*)l4;
}

// ===================== launch =====================
extern "C" void kernel_launch(void* const* d_in, const int* in_sizes, int n_in,
                              void* d_out, int out_size)
{
    const float* hidden = (const float*)d_in[0];
    const float* memory = (const float*)d_in[1];
    const float* ln1w = (const float*)d_in[4];
    const float* ln1b = (const float*)d_in[5];
    const float* ln2w = (const float*)d_in[6];
    const float* ln2b = (const float*)d_in[7];
    const float* Wq = (const float*)d_in[8];
    const float* Wk = (const float*)d_in[9];
    const float* Wv = (const float*)d_in[10];
    const float* Wo = (const float*)d_in[11];
    const float* Wg = (const float*)d_in[12];
    const float* Wu = (const float*)d_in[13];
    const float* Wd = (const float*)d_in[14];
    float* out = (float*)d_out;

    void* p;
    cudaGetSymbolAddress(&p, g_xh);  bf16* xh  = (bf16*)p;
    cudaGetSymbolAddress(&p, g_xl);  bf16* xl  = (bf16*)p;
    cudaGetSymbolAddress(&p, g_q);   float* q   = (float*)p;
    cudaGetSymbolAddress(&p, g_k);   float* k   = (float*)p;
    cudaGetSymbolAddress(&p, g_v);   float* v   = (float*)p;
    cudaGetSymbolAddress(&p, g_ah);  bf16* ah  = (bf16*)p;
    cudaGetSymbolAddress(&p, g_al);  bf16* al  = (bf16*)p;
    cudaGetSymbolAddress(&p, g_h);   float* hbuf= (float*)p;
    cudaGetSymbolAddress(&p, g_h2h); bf16* h2h = (bf16*)p;
    cudaGetSymbolAddress(&p, g_h2l); bf16* h2l = (bf16*)p;
    cudaGetSymbolAddress(&p, g_gr);  float* gr  = (float*)p;
    cudaGetSymbolAddress(&p, g_ur);  float* ur  = (float*)p;
    cudaGetSymbolAddress(&p, g_gh);  bf16* gh  = (bf16*)p;
    cudaGetSymbolAddress(&p, g_gl);  bf16* gl  = (bf16*)p;
    cudaGetSymbolAddress(&p, g_wqh); bf16* wqh = (bf16*)p;
    cudaGetSymbolAddress(&p, g_wql); bf16* wql = (bf16*)p;
    cudaGetSymbolAddress(&p, g_wkh); bf16* wkh = (bf16*)p;
    cudaGetSymbolAddress(&p, g_wkl); bf16* wkl = (bf16*)p;
    cudaGetSymbolAddress(&p, g_wvh); bf16* wvh = (bf16*)p;
    cudaGetSymbolAddress(&p, g_wvl); bf16* wvl = (bf16*)p;
    cudaGetSymbolAddress(&p, g_woh); bf16* woh = (bf16*)p;
    cudaGetSymbolAddress(&p, g_wol); bf16* wol = (bf16*)p;
    cudaGetSymbolAddress(&p, g_wgh); bf16* wgh = (bf16*)p;
    cudaGetSymbolAddress(&p, g_wgl); bf16* wgl = (bf16*)p;
    cudaGetSymbolAddress(&p, g_wuh); bf16* wuh = (bf16*)p;
    cudaGetSymbolAddress(&p, g_wul); bf16* wul = (bf16*)p;
    cudaGetSymbolAddress(&p, g_wdh); bf16* wdh = (bf16*)p;
    cudaGetSymbolAddress(&p, g_wdl); bf16* wdl = (bf16*)p;

    cudaFuncSetAttribute(gemm3_bf16, cudaFuncAttributeMaxDynamicSharedMemorySize, G_DSMEM);

    // 1. LN1 with fused split
    ln_split_kernel<<<S, 256>>>(memory, ln1w, ln1b, xh, xl);
    ln_split_kernel<<<S, 256>>>(hidden, ln1w, ln1b, xh + (size_t)S * Dm, xl + (size_t)S * Dm);

    // 2. weight splits
    {
        int nDD = Dm * Dm / 4, nFD = FF * Dm / 4;
        split_kernel<<<nDD / 256, 256>>>(Wq, wqh, wql, nDD);
        split_kernel<<<nDD / 256, 256>>>(Wk, wkh, wkl, nDD);
        split_kernel<<<nDD / 256, 256>>>(Wv, wvh, wvl, nDD);
        split_kernel<<<nDD / 256, 256>>>(Wo, woh, wol, nDD);
        split_kernel<<<nFD / 256, 256>>>(Wg, wgh, wgl, nFD);
        split_kernel<<<nFD / 256, 256>>>(Wu, wuh, wul, nFD);
        split_kernel<<<nFD / 256, 256>>>(Wd, wdh, wdl, nFD);
    }

    // 3. QKV projections (tensor cores via mma.sync)
    {
        dim3 gKV(Dm / 128, L / 128);
        gemm3_bf16<<<gKV, 256, G_DSMEM>>>(xh, xl, wkh, wkl, nullptr, k, L, Dm, Dm);
        gemm3_bf16<<<gKV, 256, G_DSMEM>>>(xh, xl, wvh, wvl, nullptr, v, L, Dm, Dm);
        dim3 gQ(Dm / 128, S / 128);
        gemm3_bf16<<<gQ, 256, G_DSMEM>>>(xh + (size_t)S * Dm, xl + (size_t)S * Dm,
                                         wqh, wql, nullptr, q, S, Dm, Dm);
    }

    // 4. RoPE
    rope_kernel<<<S, 256>>>(q, S);
    rope_kernel<<<L, 256>>>(k, L);

    // 5. sparse attention (epilogue emits bf16 hi/lo)
    {
        dim3 g(S / AM, NH);
        attn_kernel<<<g, 256>>>(q, k, v, ah, al);
    }

    // 6. output projection + residual
    {
        dim3 g(Dm / 128, S / 128);
        gemm3_bf16<<<g, 256, G_DSMEM>>>(ah, al, woh, wol, hidden, hbuf, S, Dm, Dm);
    }

    // 7. LN2 with fused split
    ln_split_kernel<<<S, 256>>>(hbuf, ln2w, ln2b, h2h, h2l);

    // 8. gate/up projections
    {
        dim3 g(FF / 128, S / 128);
        gemm3_bf16<<<g, 256, G_DSMEM>>>(h2h, h2l, wgh, wgl, nullptr, gr, S, FF, Dm);
        gemm3_bf16<<<g, 256, G_DSMEM>>>(h2h, h2l, wuh, wul, nullptr, ur, S, FF, Dm);
    }

    // 9. silu * up with fused split
    {
        int n4 = S * FF / 4;
        silu_split_kernel<<<n4 / 256, 256>>>(gr, ur, gh, gl, n4);
    }

    // 10. down projection + residual -> output
    {
        dim3 g(Dm / 128, S / 128);
        gemm3_bf16<<<g, 256, G_DSMEM>>>(gh, gl, wdh, wdl, hbuf, out, S, Dm, FF);
    }
}